// round 1
// baseline (speedup 1.0000x reference)
#include <cuda_runtime.h>
#include <cuda_bf16.h>

// Accumulators in device globals (no allocations allowed).
__device__ double g_pos_sum;
__device__ double g_neg_sum;
__device__ unsigned long long g_num_pos;

__global__ void bl_init_kernel() {
    g_pos_sum = 0.0;
    g_neg_sum = 0.0;
    g_num_pos = 0ull;
}

// One warp per row (D = 512 floats = 128 float4). Grid-stride over rows.
__global__ void __launch_bounds__(256) bl_main_kernel(
    const float* __restrict__ o1,
    const float* __restrict__ o2,
    const long long* __restrict__ tgt,
    int N)
{
    const int lane    = threadIdx.x & 31;
    const int gwarp   = (blockIdx.x * blockDim.x + threadIdx.x) >> 5;
    const int nwarps  = (gridDim.x * blockDim.x) >> 5;

    float lpos = 0.0f;
    float lneg = 0.0f;
    unsigned int lnp = 0;

    for (int r = gwarp; r < N; r += nwarps) {
        const float4* __restrict__ a = (const float4*)(o1 + (size_t)r * 512);
        const float4* __restrict__ b = (const float4*)(o2 + (size_t)r * 512);

        float dot = 0.0f, n1 = 0.0f, n2 = 0.0f;
        #pragma unroll
        for (int i = 0; i < 4; i++) {
            float4 x = a[lane + 32 * i];
            float4 y = b[lane + 32 * i];
            dot = fmaf(x.x, y.x, dot); dot = fmaf(x.y, y.y, dot);
            dot = fmaf(x.z, y.z, dot); dot = fmaf(x.w, y.w, dot);
            n1  = fmaf(x.x, x.x, n1);  n1  = fmaf(x.y, x.y, n1);
            n1  = fmaf(x.z, x.z, n1);  n1  = fmaf(x.w, x.w, n1);
            n2  = fmaf(y.x, y.x, n2);  n2  = fmaf(y.y, y.y, n2);
            n2  = fmaf(y.z, y.z, n2);  n2  = fmaf(y.w, y.w, n2);
        }

        // Warp reduction of the three partials.
        #pragma unroll
        for (int off = 16; off > 0; off >>= 1) {
            dot += __shfl_xor_sync(0xffffffffu, dot, off);
            n1  += __shfl_xor_sync(0xffffffffu, n1,  off);
            n2  += __shfl_xor_sync(0xffffffffu, n2,  off);
        }

        if (lane == 0) {
            float denom = fmaxf(sqrtf(n1) * sqrtf(n2), 1e-6f);
            float d = dot / denom;
            long long t = tgt[r];
            if (t == 1) {
                // (2/BETA) * softplus(-BETA*(d-0.5)), BETA=0.5 -> 4*softplus(x)
                float x = -0.5f * (d - 0.5f);
                float sp = fmaxf(x, 0.0f) + log1pf(expf(-fabsf(x)));
                lpos += 4.0f * sp;
                lnp  += 1u;
            } else {
                // (2/ALPHA) * softplus(ALPHA*(d-2)), ALPHA=50 -> 0.04*softplus(x)
                float x = 50.0f * (d - 2.0f);
                float sp = fmaxf(x, 0.0f) + log1pf(expf(-fabsf(x)));
                lneg += 0.04f * sp;
            }
        }
    }

    // Block reduction of per-warp (lane 0) partials.
    __shared__ float s_pos[8];
    __shared__ float s_neg[8];
    __shared__ unsigned int s_np[8];
    const int wid = threadIdx.x >> 5;
    if (lane == 0) {
        s_pos[wid] = lpos;
        s_neg[wid] = lneg;
        s_np[wid]  = lnp;
    }
    __syncthreads();
    if (threadIdx.x == 0) {
        float bp = 0.0f, bn = 0.0f;
        unsigned int np = 0;
        const int nw = blockDim.x >> 5;
        for (int i = 0; i < nw; i++) {
            bp += s_pos[i];
            bn += s_neg[i];
            np += s_np[i];
        }
        atomicAdd(&g_pos_sum, (double)bp);
        atomicAdd(&g_neg_sum, (double)bn);
        atomicAdd(&g_num_pos, (unsigned long long)np);
    }
}

__global__ void bl_finalize_kernel(float* __restrict__ out, int N) {
    double np = (double)g_num_pos;
    double nn = (double)N - np;
    double pl = g_pos_sum / (np > 1.0 ? np : 1.0);
    double nl = g_neg_sum / (nn > 1.0 ? nn : 1.0);
    out[0] = (float)(pl + nl);
}

extern "C" void kernel_launch(void* const* d_in, const int* in_sizes, int n_in,
                              void* d_out, int out_size) {
    const float*     o1  = (const float*)d_in[0];
    const float*     o2  = (const float*)d_in[1];
    const long long* tgt = (const long long*)d_in[2];
    float* out = (float*)d_out;

    const int N = in_sizes[2];  // target has one element per row

    bl_init_kernel<<<1, 1>>>();
    // Persistent-ish grid: 148 SMs * 8 blocks, 256 threads (8 warps) each.
    bl_main_kernel<<<1184, 256>>>(o1, o2, tgt, N);
    bl_finalize_kernel<<<1, 1>>>(out, N);
}

// round 2
// speedup vs baseline: 1.0425x; 1.0425x over previous
#include <cuda_runtime.h>
#include <cuda_bf16.h>

// Accumulators in device globals (no allocations allowed). Zero at module
// load; the last finishing block resets them each invocation, so the kernel
// is deterministic across graph replays.
__device__ double g_pos_sum;
__device__ double g_neg_sum;
__device__ unsigned long long g_num_pos;
__device__ unsigned int g_ticket;

__global__ void __launch_bounds__(256) bl_fused_kernel(
    const float* __restrict__ o1,
    const float* __restrict__ o2,
    const long long* __restrict__ tgt,
    float* __restrict__ out,
    int N)
{
    const int lane    = threadIdx.x & 31;
    const int gwarp   = (blockIdx.x * blockDim.x + threadIdx.x) >> 5;
    const int nwarps  = (gridDim.x * blockDim.x) >> 5;

    float lpos = 0.0f;
    float lneg = 0.0f;
    unsigned int lnp = 0;

    for (int r = gwarp; r < N; r += nwarps) {
        const float4* __restrict__ a = (const float4*)(o1 + (size_t)r * 512);
        const float4* __restrict__ b = (const float4*)(o2 + (size_t)r * 512);

        float dot = 0.0f, n1 = 0.0f, n2 = 0.0f;
        #pragma unroll
        for (int i = 0; i < 4; i++) {
            float4 x = __ldcs(&a[lane + 32 * i]);
            float4 y = __ldcs(&b[lane + 32 * i]);
            dot = fmaf(x.x, y.x, dot); dot = fmaf(x.y, y.y, dot);
            dot = fmaf(x.z, y.z, dot); dot = fmaf(x.w, y.w, dot);
            n1  = fmaf(x.x, x.x, n1);  n1  = fmaf(x.y, x.y, n1);
            n1  = fmaf(x.z, x.z, n1);  n1  = fmaf(x.w, x.w, n1);
            n2  = fmaf(y.x, y.x, n2);  n2  = fmaf(y.y, y.y, n2);
            n2  = fmaf(y.z, y.z, n2);  n2  = fmaf(y.w, y.w, n2);
        }

        // Warp reduction of the three partials.
        #pragma unroll
        for (int off = 16; off > 0; off >>= 1) {
            dot += __shfl_xor_sync(0xffffffffu, dot, off);
            n1  += __shfl_xor_sync(0xffffffffu, n1,  off);
            n2  += __shfl_xor_sync(0xffffffffu, n2,  off);
        }

        if (lane == 0) {
            float denom = fmaxf(sqrtf(n1) * sqrtf(n2), 1e-6f);
            float d = dot / denom;
            long long t = tgt[r];
            if (t == 1) {
                // (2/BETA) * softplus(-BETA*(d-0.5)), BETA=0.5 -> 4*softplus(x)
                float x = -0.5f * (d - 0.5f);
                float sp = fmaxf(x, 0.0f) + log1pf(expf(-fabsf(x)));
                lpos += 4.0f * sp;
                lnp  += 1u;
            } else {
                // (2/ALPHA) * softplus(ALPHA*(d-2)), ALPHA=50 -> 0.04*softplus(x)
                float x = 50.0f * (d - 2.0f);
                float sp = fmaxf(x, 0.0f) + log1pf(expf(-fabsf(x)));
                lneg += 0.04f * sp;
            }
        }
    }

    // Block reduction of per-warp (lane 0) partials.
    __shared__ float s_pos[8];
    __shared__ float s_neg[8];
    __shared__ unsigned int s_np[8];
    const int wid = threadIdx.x >> 5;
    if (lane == 0) {
        s_pos[wid] = lpos;
        s_neg[wid] = lneg;
        s_np[wid]  = lnp;
    }
    __syncthreads();

    if (threadIdx.x == 0) {
        float bp = 0.0f, bn = 0.0f;
        unsigned int np = 0;
        const int nw = blockDim.x >> 5;
        for (int i = 0; i < nw; i++) {
            bp += s_pos[i];
            bn += s_neg[i];
            np += s_np[i];
        }
        atomicAdd(&g_pos_sum, (double)bp);
        atomicAdd(&g_neg_sum, (double)bn);
        atomicAdd(&g_num_pos, (unsigned long long)np);

        // Make partials visible before taking a ticket.
        __threadfence();
        unsigned int ticket = atomicAdd(&g_ticket, 1u);

        if (ticket == gridDim.x - 1) {
            // Last block: finalize and reset for the next graph replay.
            double ps = g_pos_sum;
            double ns = g_neg_sum;
            double npos = (double)g_num_pos;
            double nneg = (double)N - npos;
            double pl = ps / (npos > 1.0 ? npos : 1.0);
            double nl = ns / (nneg > 1.0 ? nneg : 1.0);
            out[0] = (float)(pl + nl);

            g_pos_sum = 0.0;
            g_neg_sum = 0.0;
            g_num_pos = 0ull;
            g_ticket  = 0u;
        }
    }
}

extern "C" void kernel_launch(void* const* d_in, const int* in_sizes, int n_in,
                              void* d_out, int out_size) {
    const float*     o1  = (const float*)d_in[0];
    const float*     o2  = (const float*)d_in[1];
    const long long* tgt = (const long long*)d_in[2];
    float* out = (float*)d_out;

    const int N = in_sizes[2];  // target has one element per row

    // 148 SMs * 8 blocks, 256 threads (8 warps) each.
    bl_fused_kernel<<<1184, 256>>>(o1, o2, tgt, out, N);
}

// round 3
// speedup vs baseline: 1.1286x; 1.0825x over previous
#include <cuda_runtime.h>
#include <cuda_bf16.h>

// Accumulators in device globals (no allocations allowed). Zero at module
// load; the last finishing block resets them each invocation, so the kernel
// is deterministic across graph replays.
__device__ double g_pos_sum;
__device__ double g_neg_sum;
__device__ unsigned long long g_num_pos;
__device__ unsigned int g_ticket;

__global__ void __launch_bounds__(256) bl_fused_kernel(
    const float* __restrict__ o1,
    const float* __restrict__ o2,
    const long long* __restrict__ tgt,
    float* __restrict__ out,
    int N)
{
    const int lane    = threadIdx.x & 31;
    const int gwarp   = (blockIdx.x * blockDim.x + threadIdx.x) >> 5;
    const int nwarps  = (gridDim.x * blockDim.x) >> 5;

    float lpos = 0.0f;
    float lneg = 0.0f;
    unsigned int lnp = 0;

    for (int r = gwarp; r < N; r += nwarps) {
        const float4* __restrict__ a = (const float4*)(o1 + (size_t)r * 512);
        const float4* __restrict__ b = (const float4*)(o2 + (size_t)r * 512);

        float dot = 0.0f, n1 = 0.0f, n2 = 0.0f;
        #pragma unroll
        for (int i = 0; i < 4; i++) {
            float4 x = __ldcs(&a[lane + 32 * i]);
            float4 y = __ldcs(&b[lane + 32 * i]);
            dot = fmaf(x.x, y.x, dot); dot = fmaf(x.y, y.y, dot);
            dot = fmaf(x.z, y.z, dot); dot = fmaf(x.w, y.w, dot);
            n1  = fmaf(x.x, x.x, n1);  n1  = fmaf(x.y, x.y, n1);
            n1  = fmaf(x.z, x.z, n1);  n1  = fmaf(x.w, x.w, n1);
            n2  = fmaf(y.x, y.x, n2);  n2  = fmaf(y.y, y.y, n2);
            n2  = fmaf(y.z, y.z, n2);  n2  = fmaf(y.w, y.w, n2);
        }

        // Warp reduction of the three partials.
        #pragma unroll
        for (int off = 16; off > 0; off >>= 1) {
            dot += __shfl_xor_sync(0xffffffffu, dot, off);
            n1  += __shfl_xor_sync(0xffffffffu, n1,  off);
            n2  += __shfl_xor_sync(0xffffffffu, n2,  off);
        }

        if (lane == 0) {
            float denom = fmaxf(sqrtf(n1) * sqrtf(n2), 1e-6f);
            float d = dot / denom;
            long long t = tgt[r];
            if (t == 1) {
                // (2/BETA) * softplus(-BETA*(d-0.5)), BETA=0.5 -> 4*softplus(x)
                float x = -0.5f * (d - 0.5f);
                float sp = fmaxf(x, 0.0f) + log1pf(expf(-fabsf(x)));
                lpos += 4.0f * sp;
                lnp  += 1u;
            } else {
                // (2/ALPHA) * softplus(ALPHA*(d-2)), ALPHA=50 -> 0.04*softplus(x)
                float x = 50.0f * (d - 2.0f);
                float sp = fmaxf(x, 0.0f) + log1pf(expf(-fabsf(x)));
                lneg += 0.04f * sp;
            }
        }
    }

    // Block reduction of per-warp (lane 0) partials.
    __shared__ float s_pos[8];
    __shared__ float s_neg[8];
    __shared__ unsigned int s_np[8];
    const int wid = threadIdx.x >> 5;
    if (lane == 0) {
        s_pos[wid] = lpos;
        s_neg[wid] = lneg;
        s_np[wid]  = lnp;
    }
    __syncthreads();

    if (threadIdx.x == 0) {
        float bp = 0.0f, bn = 0.0f;
        unsigned int np = 0;
        const int nw = blockDim.x >> 5;
        for (int i = 0; i < nw; i++) {
            bp += s_pos[i];
            bn += s_neg[i];
            np += s_np[i];
        }
        atomicAdd(&g_pos_sum, (double)bp);
        atomicAdd(&g_neg_sum, (double)bn);
        atomicAdd(&g_num_pos, (unsigned long long)np);

        // Make partials visible before taking a ticket.
        __threadfence();
        unsigned int ticket = atomicAdd(&g_ticket, 1u);

        if (ticket == gridDim.x - 1) {
            // Last block: finalize and reset for the next graph replay.
            double ps = g_pos_sum;
            double ns = g_neg_sum;
            double npos = (double)g_num_pos;
            double nneg = (double)N - npos;
            double pl = ps / (npos > 1.0 ? npos : 1.0);
            double nl = ns / (nneg > 1.0 ? nneg : 1.0);
            out[0] = (float)(pl + nl);

            g_pos_sum = 0.0;
            g_neg_sum = 0.0;
            g_num_pos = 0ull;
            g_ticket  = 0u;
        }
    }
}

extern "C" void kernel_launch(void* const* d_in, const int* in_sizes, int n_in,
                              void* d_out, int out_size) {
    const float*     o1  = (const float*)d_in[0];
    const float*     o2  = (const float*)d_in[1];
    const long long* tgt = (const long long*)d_in[2];
    float* out = (float*)d_out;

    const int N = in_sizes[2];  // target has one element per row

    // Launch exactly ONE resident wave: blocks/SM from the occupancy
    // calculator (accounts for actual reg usage) x SM count. Pure host
    // queries — graph-capture safe, no allocations, deterministic.
    int dev = 0;
    cudaGetDevice(&dev);
    int num_sms = 148;
    cudaDeviceGetAttribute(&num_sms, cudaDevAttrMultiProcessorCount, dev);
    int blocks_per_sm = 6;
    cudaOccupancyMaxActiveBlocksPerMultiprocessor(&blocks_per_sm,
                                                  bl_fused_kernel, 256, 0);
    if (blocks_per_sm < 1) blocks_per_sm = 1;
    int grid = num_sms * blocks_per_sm;

    bl_fused_kernel<<<grid, 256>>>(o1, o2, tgt, out, N);
}